// round 12
// baseline (speedup 1.0000x reference)
#include <cuda_runtime.h>
#include <stdint.h>

// GCN layer, atomic-free aggregation via counting-sort by dst.
// src/dst are INT32 (JAX with x64 disabled).
// R12 = proven R6 structure (fp32 gather 12thr/node, thread-per-node finalize)
//       + x4-unrolled gather (MLP) + int4-vectorized degree/bucket.

#define N_NODES   50000
#define N_EDGES   1600000
#define D         48
#define DV        12            // float4 chunks per row
#define SCAN_B    256
#define SCAN_G    ((N_NODES + SCAN_B - 1) / SCAN_B)   // 196

// Scratch (__device__ globals; no allocation allowed)
__device__ float4 g_agg[N_NODES * DV];       // 9.6 MB aggregated messages
__device__ float4 g_featci[N_NODES * DV];    // 9.6 MB feat * ci (premultiplied)
__device__ int    g_outdeg[N_NODES];
__device__ int    g_indeg[N_NODES];
__device__ int    g_off[N_NODES];            // exclusive prefix of indeg
__device__ int    g_cursor[N_NODES];         // bucket fill cursors
__device__ int    g_sorted_src[N_EDGES];     // src ids grouped by dst (6.4 MB)
__device__ int    g_blocksum[SCAN_G];
__device__ int    g_blockbase[SCAN_G];

__device__ __forceinline__ int clamp_node(int v) {
    return ((unsigned)v < (unsigned)N_NODES) ? v : 0;
}

// ---------------------------------------------------------------------------
__global__ void zero_kernel() {
    int i = blockIdx.x * blockDim.x + threadIdx.x;
    if (i < N_NODES) { g_outdeg[i] = 0; g_indeg[i] = 0; }
}

// ---------------------------------------------------------------------------
// 4 edges per thread via int4 loads; 8 independent REDs batched for pipelining.
__global__ void degree_kernel(const int4* __restrict__ src4,
                              const int4* __restrict__ dst4) {
    int t = blockIdx.x * blockDim.x + threadIdx.x;
    if (t >= N_EDGES / 4) return;
    int4 s = src4[t];
    int4 d = dst4[t];
    atomicAdd(&g_outdeg[clamp_node(s.x)], 1);
    atomicAdd(&g_outdeg[clamp_node(s.y)], 1);
    atomicAdd(&g_outdeg[clamp_node(s.z)], 1);
    atomicAdd(&g_outdeg[clamp_node(s.w)], 1);
    atomicAdd(&g_indeg[clamp_node(d.x)], 1);
    atomicAdd(&g_indeg[clamp_node(d.y)], 1);
    atomicAdd(&g_indeg[clamp_node(d.z)], 1);
    atomicAdd(&g_indeg[clamp_node(d.w)], 1);
}

// ---------------------------------------------------------------------------
// featci[n] = feat[n] * rsqrt(max(outdeg[n],1)), 12 threads per node
__global__ void premul_kernel(const float4* __restrict__ feat4) {
    unsigned idx = blockIdx.x * blockDim.x + threadIdx.x;
    if (idx >= (unsigned)N_NODES * DV) return;
    unsigned n = idx / DV;
    float ci = rsqrtf(fmaxf((float)g_outdeg[n], 1.0f));
    float4 v = feat4[idx];
    v.x *= ci; v.y *= ci; v.z *= ci; v.w *= ci;
    g_featci[idx] = v;
}

// ---------------------------------------------------------------------------
// Three-phase exclusive scan of g_indeg -> g_off, g_cursor
__global__ void scanA_kernel() {
    __shared__ int sh[SCAN_B];
    int i = blockIdx.x * SCAN_B + threadIdx.x;
    sh[threadIdx.x] = (i < N_NODES) ? g_indeg[i] : 0;
    __syncthreads();
    for (int off = SCAN_B / 2; off > 0; off >>= 1) {
        if (threadIdx.x < off) sh[threadIdx.x] += sh[threadIdx.x + off];
        __syncthreads();
    }
    if (threadIdx.x == 0) g_blocksum[blockIdx.x] = sh[0];
}

__global__ void scanB_kernel() {
    __shared__ int sh[SCAN_G];
    int t = threadIdx.x;
    if (t < SCAN_G) sh[t] = g_blocksum[t];
    __syncthreads();
    for (int off = 1; off < SCAN_G; off <<= 1) {
        int v = (t >= off && t < SCAN_G) ? sh[t - off] : 0;
        __syncthreads();
        if (t < SCAN_G) sh[t] += v;
        __syncthreads();
    }
    if (t < SCAN_G) g_blockbase[t] = (t == 0) ? 0 : sh[t - 1];
}

__global__ void scanC_kernel() {
    __shared__ int sh[SCAN_B];
    int i = blockIdx.x * SCAN_B + threadIdx.x;
    int t = threadIdx.x;
    int v = (i < N_NODES) ? g_indeg[i] : 0;
    sh[t] = v;
    __syncthreads();
    for (int off = 1; off < SCAN_B; off <<= 1) {
        int u = (t >= off) ? sh[t - off] : 0;
        __syncthreads();
        sh[t] += u;
        __syncthreads();
    }
    if (i < N_NODES) {
        int excl = g_blockbase[blockIdx.x] + sh[t] - v;
        g_off[i]    = excl;
        g_cursor[i] = excl;
    }
}

// ---------------------------------------------------------------------------
// Bucket edges by dst (4 edges/thread): sorted_src[pos] = src
__global__ void bucket_kernel(const int4* __restrict__ src4,
                              const int4* __restrict__ dst4) {
    int t = blockIdx.x * blockDim.x + threadIdx.x;
    if (t >= N_EDGES / 4) return;
    int4 s = src4[t];
    int4 d = dst4[t];
    int p0 = atomicAdd(&g_cursor[clamp_node(d.x)], 1);
    int p1 = atomicAdd(&g_cursor[clamp_node(d.y)], 1);
    int p2 = atomicAdd(&g_cursor[clamp_node(d.z)], 1);
    int p3 = atomicAdd(&g_cursor[clamp_node(d.w)], 1);
    if ((unsigned)p0 < (unsigned)N_EDGES) g_sorted_src[p0] = clamp_node(s.x);
    if ((unsigned)p1 < (unsigned)N_EDGES) g_sorted_src[p1] = clamp_node(s.y);
    if ((unsigned)p2 < (unsigned)N_EDGES) g_sorted_src[p2] = clamp_node(s.z);
    if ((unsigned)p3 < (unsigned)N_EDGES) g_sorted_src[p3] = clamp_node(s.w);
}

// ---------------------------------------------------------------------------
// Atomic-free gather: 12 threads per node, thread owns one float4 column.
// x4 unrolled: 4 independent index loads, then 4 independent row loads in
// flight per round (latency-bound loop -> MLP is the lever).
__global__ void gather_kernel() {
    unsigned idx = blockIdx.x * blockDim.x + threadIdx.x;
    if (idx >= (unsigned)N_NODES * DV) return;
    unsigned n = idx / DV;
    unsigned c = idx - n * DV;

    int beg = g_off[n];
    int cnt = g_indeg[n];

    float4 acc = make_float4(0.f, 0.f, 0.f, 0.f);
    int k = 0;
    for (; k + 4 <= cnt; k += 4) {
        int s0 = g_sorted_src[beg + k + 0];
        int s1 = g_sorted_src[beg + k + 1];
        int s2 = g_sorted_src[beg + k + 2];
        int s3 = g_sorted_src[beg + k + 3];
        float4 v0 = g_featci[(unsigned)s0 * DV + c];
        float4 v1 = g_featci[(unsigned)s1 * DV + c];
        float4 v2 = g_featci[(unsigned)s2 * DV + c];
        float4 v3 = g_featci[(unsigned)s3 * DV + c];
        acc.x += v0.x + v1.x + v2.x + v3.x;
        acc.y += v0.y + v1.y + v2.y + v3.y;
        acc.z += v0.z + v1.z + v2.z + v3.z;
        acc.w += v0.w + v1.w + v2.w + v3.w;
    }
    for (; k < cnt; k++) {
        int s0 = g_sorted_src[beg + k];
        float4 v0 = g_featci[(unsigned)s0 * DV + c];
        acc.x += v0.x; acc.y += v0.y; acc.z += v0.z; acc.w += v0.w;
    }
    g_agg[idx] = acc;
}

// ---------------------------------------------------------------------------
// h = indeg>0 ? agg*cj : feat ; out = relu(h @ W^T + b)
// Thread-per-node: W reads are warp-uniform -> smem broadcast, conflict-free.
__global__ void finalize_kernel(const float* __restrict__ feat,
                                const float* __restrict__ W,
                                const float* __restrict__ b,
                                float* __restrict__ out) {
    __shared__ float Ws[D * D];
    __shared__ float bs[D];
    for (int i = threadIdx.x; i < D * D; i += blockDim.x) Ws[i] = W[i];
    if (threadIdx.x < D) bs[threadIdx.x] = b[threadIdx.x];
    __syncthreads();

    int n = blockIdx.x * blockDim.x + threadIdx.x;
    if (n >= N_NODES) return;

    int indeg = g_indeg[n];
    float cj = rsqrtf(fmaxf((float)indeg, 1.0f));
    const float* aggp = (const float*)g_agg;
    const float* hp   = (indeg > 0) ? (aggp + (size_t)n * D) : (feat + (size_t)n * D);
    float scale       = (indeg > 0) ? cj : 1.0f;

    float acc[D];
#pragma unroll
    for (int o = 0; o < D; o++) acc[o] = bs[o];

#pragma unroll 4
    for (int i = 0; i < D; i++) {
        float hi = hp[i] * scale;
#pragma unroll
        for (int o = 0; o < D; o++) acc[o] += hi * Ws[o * D + i];
    }

    float4* out4 = (float4*)(out + (size_t)n * D);
#pragma unroll
    for (int k = 0; k < DV; k++) {
        float4 v;
        v.x = fmaxf(acc[4 * k + 0], 0.f);
        v.y = fmaxf(acc[4 * k + 1], 0.f);
        v.z = fmaxf(acc[4 * k + 2], 0.f);
        v.w = fmaxf(acc[4 * k + 3], 0.f);
        out4[k] = v;
    }
}

// ---------------------------------------------------------------------------
extern "C" void kernel_launch(void* const* d_in, const int* in_sizes, int n_in,
                              void* d_out, int out_size) {
    const float* feat = (const float*)d_in[0];
    const int*   src  = (const int*)d_in[1];    // int32
    const int*   dst  = (const int*)d_in[2];
    const float* W    = (const float*)d_in[3];
    const float* b    = (const float*)d_in[4];
    float*       out  = (float*)d_out;
    (void)in_sizes; (void)n_in; (void)out_size;

    const int TB = 256;

    zero_kernel<<<(N_NODES + TB - 1) / TB, TB>>>();
    degree_kernel<<<(N_EDGES / 4 + TB - 1) / TB, TB>>>(
        (const int4*)src, (const int4*)dst);
    {
        unsigned total = (unsigned)N_NODES * DV;   // 600000
        premul_kernel<<<(total + TB - 1) / TB, TB>>>((const float4*)feat);
    }
    scanA_kernel<<<SCAN_G, SCAN_B>>>();
    scanB_kernel<<<1, SCAN_B>>>();
    scanC_kernel<<<SCAN_G, SCAN_B>>>();
    bucket_kernel<<<(N_EDGES / 4 + TB - 1) / TB, TB>>>(
        (const int4*)src, (const int4*)dst);
    {
        unsigned total = (unsigned)N_NODES * DV;   // 600000
        gather_kernel<<<(total + 191) / 192, 192>>>();
    }
    finalize_kernel<<<(N_NODES + TB - 1) / TB, TB>>>(feat, W, b, out);
}

// round 17
// speedup vs baseline: 1.4964x; 1.4964x over previous
#include <cuda_runtime.h>
#include <cuda_fp16.h>
#include <stdint.h>

// GCN layer, atomic-free aggregation via counting-sort by dst.
// src/dst are INT32 (JAX with x64 disabled).
// R16 = resubmission of R13 (infra failure, never measured):
//       exact R6 structure (103.2us proven: scalar degree/bucket, x2 gather,
//       separate finalize) with ONE change: premultiplied features in fp16,
//       12 threads/node preserved (each thread owns 4 halves = uint2).

#define N_NODES   50000
#define N_EDGES   1600000
#define D         48
#define DV        12            // 4-element chunks per row
#define SCAN_B    256
#define SCAN_G    ((N_NODES + SCAN_B - 1) / SCAN_B)   // 196

// Scratch (__device__ globals; no allocation allowed)
__device__ float4 g_agg[N_NODES * DV];        // 9.6 MB aggregated messages (fp32)
__device__ uint2  g_featci_h[N_NODES * DV];   // 4.8 MB feat*ci fp16, 4 halves/uint2
__device__ int    g_outdeg[N_NODES];
__device__ int    g_indeg[N_NODES];
__device__ int    g_off[N_NODES];
__device__ int    g_cursor[N_NODES];
__device__ int    g_sorted_src[N_EDGES];      // 6.4 MB
__device__ int    g_blocksum[SCAN_G];
__device__ int    g_blockbase[SCAN_G];

__device__ __forceinline__ int clamp_node(int v) {
    return ((unsigned)v < (unsigned)N_NODES) ? v : 0;
}

// ---------------------------------------------------------------------------
__global__ void zero_kernel() {
    int i = blockIdx.x * blockDim.x + threadIdx.x;
    if (i < N_NODES) { g_outdeg[i] = 0; g_indeg[i] = 0; }
}

// ---------------------------------------------------------------------------
__global__ void degree_kernel(const int* __restrict__ src,
                              const int* __restrict__ dst) {
    int e = blockIdx.x * blockDim.x + threadIdx.x;
    if (e >= N_EDGES) return;
    atomicAdd(&g_outdeg[clamp_node(src[e])], 1);
    atomicAdd(&g_indeg[clamp_node(dst[e])], 1);
}

// ---------------------------------------------------------------------------
// featci_h[idx] = fp16(feat4[idx] * ci), 12 threads per node, 1 float4 -> uint2.
__global__ void premul_kernel(const float4* __restrict__ feat4) {
    unsigned idx = blockIdx.x * blockDim.x + threadIdx.x;
    if (idx >= (unsigned)N_NODES * DV) return;
    unsigned n = idx / DV;
    float ci = rsqrtf(fmaxf((float)g_outdeg[n], 1.0f));
    float4 v = feat4[idx];
    uint2 o;
    __half2* ph = (__half2*)&o;
    ph[0] = __floats2half2_rn(v.x * ci, v.y * ci);
    ph[1] = __floats2half2_rn(v.z * ci, v.w * ci);
    g_featci_h[idx] = o;
}

// ---------------------------------------------------------------------------
// Three-phase exclusive scan of g_indeg -> g_off, g_cursor
__global__ void scanA_kernel() {
    __shared__ int sh[SCAN_B];
    int i = blockIdx.x * SCAN_B + threadIdx.x;
    sh[threadIdx.x] = (i < N_NODES) ? g_indeg[i] : 0;
    __syncthreads();
    for (int off = SCAN_B / 2; off > 0; off >>= 1) {
        if (threadIdx.x < off) sh[threadIdx.x] += sh[threadIdx.x + off];
        __syncthreads();
    }
    if (threadIdx.x == 0) g_blocksum[blockIdx.x] = sh[0];
}

__global__ void scanB_kernel() {
    __shared__ int sh[SCAN_G];
    int t = threadIdx.x;
    if (t < SCAN_G) sh[t] = g_blocksum[t];
    __syncthreads();
    for (int off = 1; off < SCAN_G; off <<= 1) {
        int v = (t >= off && t < SCAN_G) ? sh[t - off] : 0;
        __syncthreads();
        if (t < SCAN_G) sh[t] += v;
        __syncthreads();
    }
    if (t < SCAN_G) g_blockbase[t] = (t == 0) ? 0 : sh[t - 1];
}

__global__ void scanC_kernel() {
    __shared__ int sh[SCAN_B];
    int i = blockIdx.x * SCAN_B + threadIdx.x;
    int t = threadIdx.x;
    int v = (i < N_NODES) ? g_indeg[i] : 0;
    sh[t] = v;
    __syncthreads();
    for (int off = 1; off < SCAN_B; off <<= 1) {
        int u = (t >= off) ? sh[t - off] : 0;
        __syncthreads();
        sh[t] += u;
        __syncthreads();
    }
    if (i < N_NODES) {
        int excl = g_blockbase[blockIdx.x] + sh[t] - v;
        g_off[i]    = excl;
        g_cursor[i] = excl;
    }
}

// ---------------------------------------------------------------------------
// Bucket edges by dst: sorted_src[pos] = src
__global__ void bucket_kernel(const int* __restrict__ src,
                              const int* __restrict__ dst) {
    int e = blockIdx.x * blockDim.x + threadIdx.x;
    if (e >= N_EDGES) return;
    int d = clamp_node(dst[e]);
    int pos = atomicAdd(&g_cursor[d], 1);
    if ((unsigned)pos < (unsigned)N_EDGES)
        g_sorted_src[pos] = clamp_node(src[e]);
}

// ---------------------------------------------------------------------------
// Atomic-free gather: 12 threads per node, thread owns 4 halves (uint2).
// Same thread/warp structure as the proven fp32 version; half the bytes.
// fp32 accumulation; writes fp32 g_agg.
__global__ void gather_kernel() {
    unsigned idx = blockIdx.x * blockDim.x + threadIdx.x;
    if (idx >= (unsigned)N_NODES * DV) return;
    unsigned n = idx / DV;
    unsigned c = idx - n * DV;

    int beg = g_off[n];
    int cnt = g_indeg[n];

    float a0 = 0.f, a1 = 0.f, a2 = 0.f, a3 = 0.f;
    int k = 0;
    for (; k + 2 <= cnt; k += 2) {
        int s0 = g_sorted_src[beg + k + 0];
        int s1 = g_sorted_src[beg + k + 1];
        uint2 u0 = g_featci_h[(unsigned)s0 * DV + c];
        uint2 u1 = g_featci_h[(unsigned)s1 * DV + c];
        const __half2* p0 = (const __half2*)&u0;
        const __half2* p1 = (const __half2*)&u1;
        float2 f;
        f = __half22float2(p0[0]); a0 += f.x; a1 += f.y;
        f = __half22float2(p0[1]); a2 += f.x; a3 += f.y;
        f = __half22float2(p1[0]); a0 += f.x; a1 += f.y;
        f = __half22float2(p1[1]); a2 += f.x; a3 += f.y;
    }
    if (k < cnt) {
        int s0 = g_sorted_src[beg + k];
        uint2 u0 = g_featci_h[(unsigned)s0 * DV + c];
        const __half2* p0 = (const __half2*)&u0;
        float2 f;
        f = __half22float2(p0[0]); a0 += f.x; a1 += f.y;
        f = __half22float2(p0[1]); a2 += f.x; a3 += f.y;
    }
    g_agg[idx] = make_float4(a0, a1, a2, a3);
}

// ---------------------------------------------------------------------------
// h = indeg>0 ? agg*cj : feat ; out = relu(h @ W^T + b)
// Thread-per-node: W reads warp-uniform -> smem broadcast, conflict-free.
__global__ void finalize_kernel(const float* __restrict__ feat,
                                const float* __restrict__ W,
                                const float* __restrict__ b,
                                float* __restrict__ out) {
    __shared__ float Ws[D * D];
    __shared__ float bs[D];
    for (int i = threadIdx.x; i < D * D; i += blockDim.x) Ws[i] = W[i];
    if (threadIdx.x < D) bs[threadIdx.x] = b[threadIdx.x];
    __syncthreads();

    int n = blockIdx.x * blockDim.x + threadIdx.x;
    if (n >= N_NODES) return;

    int indeg = g_indeg[n];
    float cj = rsqrtf(fmaxf((float)indeg, 1.0f));
    const float* aggp = (const float*)g_agg;
    const float* hp   = (indeg > 0) ? (aggp + (size_t)n * D) : (feat + (size_t)n * D);
    float scale       = (indeg > 0) ? cj : 1.0f;

    float acc[D];
#pragma unroll
    for (int o = 0; o < D; o++) acc[o] = bs[o];

#pragma unroll 4
    for (int i = 0; i < D; i++) {
        float hi = hp[i] * scale;
#pragma unroll
        for (int o = 0; o < D; o++) acc[o] += hi * Ws[o * D + i];
    }

    float4* out4 = (float4*)(out + (size_t)n * D);
#pragma unroll
    for (int k = 0; k < DV; k++) {
        float4 v;
        v.x = fmaxf(acc[4 * k + 0], 0.f);
        v.y = fmaxf(acc[4 * k + 1], 0.f);
        v.z = fmaxf(acc[4 * k + 2], 0.f);
        v.w = fmaxf(acc[4 * k + 3], 0.f);
        out4[k] = v;
    }
}

// ---------------------------------------------------------------------------
extern "C" void kernel_launch(void* const* d_in, const int* in_sizes, int n_in,
                              void* d_out, int out_size) {
    const float* feat = (const float*)d_in[0];
    const int*   src  = (const int*)d_in[1];    // int32
    const int*   dst  = (const int*)d_in[2];
    const float* W    = (const float*)d_in[3];
    const float* b    = (const float*)d_in[4];
    float*       out  = (float*)d_out;
    (void)in_sizes; (void)n_in; (void)out_size;

    const int TB = 256;

    zero_kernel<<<(N_NODES + TB - 1) / TB, TB>>>();
    degree_kernel<<<(N_EDGES + TB - 1) / TB, TB>>>(src, dst);
    {
        unsigned total = (unsigned)N_NODES * DV;   // 600000
        premul_kernel<<<(total + TB - 1) / TB, TB>>>((const float4*)feat);
    }
    scanA_kernel<<<SCAN_G, SCAN_B>>>();
    scanB_kernel<<<1, SCAN_B>>>();
    scanC_kernel<<<SCAN_G, SCAN_B>>>();
    bucket_kernel<<<(N_EDGES + TB - 1) / TB, TB>>>(src, dst);
    {
        unsigned total = (unsigned)N_NODES * DV;   // 600000
        gather_kernel<<<(total + 191) / 192, 192>>>();
    }
    finalize_kernel<<<(N_NODES + TB - 1) / TB, TB>>>(feat, W, b, out);
}